// round 15
// baseline (speedup 1.0000x reference)
#include <cuda_runtime.h>
#include <math.h>

// ---------------------------------------------------------------------------
// RadarPillarFeatureNet on GB300 — single fused data pass (R12 dual-pillar
// structure; butterfly max in split lo/hi float lanes -> scalar FMNMX):
//   pack_kernel:   raw weights -> packed pair layout -> __constant__ c_cf
//   fused_kernel:  TWO pillars/iter: RAW channel max (f32x2 GEMVs, dual
//                  float-lane butterfly) AND 63-moment accumulation.
//   reduce_kernel: deterministic tree-reduce of per-block moment partials.
//   finalize:      moments -> per-channel scale/shift (layernorm fold).
//   affine:        out = relu(scale*rawmax + shift)  (scale>0 => commutes).
// ---------------------------------------------------------------------------

typedef unsigned long long u64;

namespace {
constexpr int   MPTS   = 32;
constexpr float VXc = 0.2f, VYc = 0.2f, XOFF = 0.1f, YOFF = -39.9f;
constexpr int   NMOM   = 63;
constexpr int   WARPS_C = 4;
constexpr int   BLOCKS_C = 888;
}

__device__ float g_partials[NMOM * BLOCKS_C];   // [mom][block] (transposed)
__device__ float g_mom_sum[NMOM];
// Packed RAW weights (float2 "u" pairs), viewed as u64[160]:
//  [0..63] b0 p*8+c | [64..79] b1 | [80..95] b2 | [96..127] b3 | [128..159] zeros
__device__ __align__(16) float g_coeff[320];
__constant__ __align__(16) u64 c_cf[160];
__device__ float g_affine[128];   // [0..63] scale, [64..127] shift

__device__ __forceinline__ u64 pk2(float a, float b) {
  u64 r; asm("mov.b64 %0, {%1,%2};" : "=l"(r) : "f"(a), "f"(b)); return r;
}
__device__ __forceinline__ u64 ffma2(u64 a, u64 b, u64 c) {
  u64 d; asm("fma.rn.f32x2 %0, %1, %2, %3;" : "=l"(d) : "l"(a), "l"(b), "l"(c)); return d;
}
__device__ __forceinline__ u64 add2(u64 a, u64 b) {
  u64 d; asm("add.rn.f32x2 %0, %1, %2;" : "=l"(d) : "l"(a), "l"(b)); return d;
}
__device__ __forceinline__ void unpk2(u64 x, float& lo, float& hi) {
  asm("mov.b64 {%0,%1}, %2;" : "=f"(lo), "=f"(hi) : "l"(x));
}
__device__ __forceinline__ u64 shfl64(u64 x, int o) {
  return __shfl_xor_sync(0xffffffffu, x, o);
}
__device__ __forceinline__ float shflf(float x, int o) {
  return __shfl_xor_sync(0xffffffffu, x, o);
}
__device__ __forceinline__ void cp16(unsigned s, const void* g) {
  asm volatile("cp.async.cg.shared.global [%0], [%1], 16;" :: "r"(s), "l"(g));
}

// f32x2-packed warp sums for the 5 feature columns.
__device__ __forceinline__ void make_feat(const float f[9], int np, float cx, float cy,
                                          int lane, float v[14]) {
  u64 s01 = pk2(f[0], f[1]);
  u64 s23 = pk2(f[2], f[3]);
  float s4 = f[4];
#pragma unroll
  for (int o = 16; o; o >>= 1) {
    s01 = add2(s01, shfl64(s01, o));
    s23 = add2(s23, shfl64(s23, o));
    s4 += shflf(s4, o);
  }
  float sx, sy, sz, s3;
  unpk2(s01, sx, sy);
  unpk2(s23, sz, s3);
  float inv  = 1.0f / (float)np;
  float mask = (lane < np) ? 1.0f : 0.0f;
  v[0] = (f[0] - cx) * mask;
  v[1] = (f[1] - cy) * mask;
  v[2] = f[2] * mask;  v[3] = f[3] * mask;  v[4] = f[4] * mask;
  v[5] = f[5] * mask;  v[6] = f[6] * mask;  v[7] = f[7] * mask;  v[8] = f[8] * mask;
  v[9]  = (f[0] - sx * inv) * mask;
  v[10] = (f[1] - sy * inv) * mask;
  v[11] = (f[2] - sz * inv) * mask;
  v[12] = (f[3] - s3 * inv) * mask;
  v[13] = (f[4] - s4 * inv) * mask;
}

// Dual butterfly reduce in SPLIT float lanes (lo/hi of each channel pair).
// In: two pillars' GEMV accumulators (u64[8] each). Out: fully reduced
// channel pair (lane & 7) for each pillar as (lo, hi) floats.
__device__ __forceinline__ void branch_reduce2(const u64 aA[8], const u64 aB[8],
                                               int lane,
                                               float& rAlo, float& rAhi,
                                               float& rBlo, float& rBhi) {
  float Alo[8], Ahi[8], Blo[8], Bhi[8];
#pragma unroll
  for (int i = 0; i < 8; i++) { unpk2(aA[i], Alo[i], Ahi[i]); unpk2(aB[i], Blo[i], Bhi[i]); }
#pragma unroll
  for (int b = 2; b >= 0; b--) {
    const int  o    = 1 << b;
    const int  half = 1 << b;
    const bool bit  = (lane >> b) & 1;
#pragma unroll
    for (int i = 0; i < half; i++) {
      const float sAl = bit ? Alo[i] : Alo[i + half];
      const float sAh = bit ? Ahi[i] : Ahi[i + half];
      const float sBl = bit ? Blo[i] : Blo[i + half];
      const float sBh = bit ? Bhi[i] : Bhi[i + half];
      const float gAl = shflf(sAl, o), gAh = shflf(sAh, o);
      const float gBl = shflf(sBl, o), gBh = shflf(sBh, o);
      Alo[i] = fmaxf(bit ? Alo[i + half] : Alo[i], gAl);
      Ahi[i] = fmaxf(bit ? Ahi[i + half] : Ahi[i], gAh);
      Blo[i] = fmaxf(bit ? Blo[i + half] : Blo[i], gBl);
      Bhi[i] = fmaxf(bit ? Bhi[i + half] : Bhi[i], gBh);
    }
  }
  float al = Alo[0], ah = Ahi[0], bl = Blo[0], bh = Bhi[0];
  al = fmaxf(al, shflf(al, 8));   ah = fmaxf(ah, shflf(ah, 8));
  bl = fmaxf(bl, shflf(bl, 8));   bh = fmaxf(bh, shflf(bh, 8));
  al = fmaxf(al, shflf(al, 16));  ah = fmaxf(ah, shflf(ah, 16));
  bl = fmaxf(bl, shflf(bl, 16));  bh = fmaxf(bh, shflf(bh, 16));
  rAlo = al; rAhi = ah; rBlo = bl; rBhi = bh;
}

// Scalar moment accumulation for one pillar's feature vector v.
__device__ __forceinline__ void accum_moments(float acc[NMOM], const float v[14]) {
#pragma unroll
  for (int i = 0; i < 14; i++) acc[i] += v[i];
  const int L1[8] = {0, 1, 2, 5, 6, 7, 8, 9};
  int k = 14;
#pragma unroll
  for (int i = 0; i < 8; i++)
#pragma unroll
    for (int j = i; j < 8; j++) acc[k++] += v[L1[i]] * v[L1[j]];
  acc[50] += v[3] * v[3];   acc[51] += v[3] * v[10];  acc[52] += v[10] * v[10];
  acc[53] += v[4] * v[4];   acc[54] += v[4] * v[11];  acc[55] += v[11] * v[11];
  acc[56] += v[0] * v[12];  acc[57] += v[0] * v[13];
  acc[58] += v[1] * v[12];  acc[59] += v[1] * v[13];
  acc[60] += v[12] * v[12]; acc[61] += v[12] * v[13]; acc[62] += v[13] * v[13];
}

// ---------------------------------------------------------------------------
__global__ void shift_kernel() {}   // ncu capture-window shifter (no-op)

// Pack RAW weights into the pair layout (shifts = 0).
__global__ void pack_kernel(const float* __restrict__ w1, const float* __restrict__ w2,
                            const float* __restrict__ w3, const float* __restrict__ w4) {
  const int t = threadIdx.x;
  if (t >= 64) return;
  const int br = t >> 4, uu = t & 15, half = uu & 1, p = uu >> 1;
  g_coeff[256 + t] = 0.f;
  if (br == 0) {
    for (int c = 0; c < 8; c++) g_coeff[(p * 8 + c) * 2 + half] = w1[uu * 8 + c];
  } else if (br == 1) {
    for (int c = 0; c < 2; c++) g_coeff[(64 + p * 2 + c) * 2 + half] = w2[uu * 2 + c];
  } else if (br == 2) {
    for (int c = 0; c < 2; c++) g_coeff[(80 + p * 2 + c) * 2 + half] = w3[uu * 2 + c];
  } else {
    for (int c = 0; c < 4; c++) g_coeff[(96 + p * 4 + c) * 2 + half] = w4[uu * 4 + c];
  }
}

// ---------------------------------------------------------------------------
__device__ __forceinline__ void stage_pillar(const float* feats, int n,
                                             float* dst, int lane) {
  const float4* src = reinterpret_cast<const float4*>(feats + (size_t)n * 288);
  unsigned base = (unsigned)__cvta_generic_to_shared(dst);
  cp16(base + lane * 16, src + lane);
  cp16(base + (lane + 32) * 16, src + lane + 32);
  if (lane < 8) cp16(base + (lane + 64) * 16, src + lane + 64);
}

// Fused: raw per-channel max into out, AND moment partials into g_partials.
__global__ __launch_bounds__(WARPS_C * 32, 3)
void fused_kernel(const float* __restrict__ feats, const int* __restrict__ nump,
                  const int* __restrict__ coors, float* __restrict__ out, int nP) {
  __shared__ __align__(16) float s_stage[WARPS_C][4][288];
  __shared__ float s_red[WARPS_C][NMOM];
  const int tid  = threadIdx.x;
  const int warp = tid >> 5;
  const int lane = tid & 31;

  const int gw = blockIdx.x * WARPS_C + warp;
  const int W  = BLOCKS_C * WARPS_C;
  const int sel = lane >> 3;

  float mom[NMOM];
#pragma unroll
  for (int i = 0; i < NMOM; i++) mom[i] = 0.f;

  if (gw < nP)     stage_pillar(feats, gw,     &s_stage[warp][0][0], lane);
  if (gw + W < nP) stage_pillar(feats, gw + W, &s_stage[warp][1][0], lane);
  asm volatile("cp.async.commit_group;");

  int buf = 0;
  for (int n = gw; n < nP; n += 2 * W) {
    const int nB = n + W;
    const bool bv = nB < nP;

    const int   npA = nump[n];
    const float cxA = (float)coors[n * 4 + 3] * VXc + XOFF;
    const float cyA = (float)coors[n * 4 + 2] * VYc + YOFF;
    int npB = 1; float cxB = 0.f, cyB = 0.f;
    if (bv) {
      npB = nump[nB];
      cxB = (float)coors[nB * 4 + 3] * VXc + XOFF;
      cyB = (float)coors[nB * 4 + 2] * VYc + YOFF;
    }

    const int nnA = n + 2 * W, nnB = n + 3 * W;
    if (nnA < nP) stage_pillar(feats, nnA, &s_stage[warp][buf ^ 2][0], lane);
    if (nnB < nP) stage_pillar(feats, nnB, &s_stage[warp][(buf ^ 2) + 1][0], lane);
    asm volatile("cp.async.commit_group;");
    asm volatile("cp.async.wait_group 1;");
    __syncwarp();

    float vA[14], vB[14];
    {
      const float* sA = s_stage[warp][buf];
      float fA[9];
#pragma unroll
      for (int c = 0; c < 9; c++) fA[c] = sA[lane * 9 + c];
      make_feat(fA, npA, cxA, cyA, lane, vA);
    }
    if (bv) {
      const float* sB = s_stage[warp][buf + 1];
      float fB[9];
#pragma unroll
      for (int c = 0; c < 9; c++) fB[c] = sB[lane * 9 + c];
      make_feat(fB, npB, cxB, cyB, lane, vB);
    } else {
#pragma unroll
      for (int c = 0; c < 14; c++) vB[c] = 0.f;
    }

    // moments (both pillars; vB==0 when invalid)
    accum_moments(mom, vA);
    accum_moments(mom, vB);

    float finAlo = 0.f, finAhi = 0.f, finBlo = 0.f, finBhi = 0.f;
    u64 aA[8], aB[8];
    // ---- branch 0 ----
    {
      const int M[8] = {0, 1, 2, 5, 6, 7, 8, 9};
#pragma unroll
      for (int p = 0; p < 8; p++) { const u64 s = c_cf[128 + p]; aA[p] = s; aB[p] = s; }
#pragma unroll
      for (int c = 0; c < 8; c++) {
        const u64 mA = pk2(vA[M[c]], vA[M[c]]);
        const u64 mB = pk2(vB[M[c]], vB[M[c]]);
#pragma unroll
        for (int p = 0; p < 8; p++) {
          const u64 w = c_cf[p * 8 + c];
          aA[p] = ffma2(mA, w, aA[p]);
          aB[p] = ffma2(mB, w, aB[p]);
        }
      }
      float rAl, rAh, rBl, rBh;
      branch_reduce2(aA, aB, lane, rAl, rAh, rBl, rBh);
      if (sel == 0) { finAlo = rAl; finAhi = rAh; finBlo = rBl; finBhi = rBh; }
    }
    // ---- branch 1 ----
    {
      const u64 mA0 = pk2(vA[3], vA[3]),  mA1 = pk2(vA[10], vA[10]);
      const u64 mB0 = pk2(vB[3], vB[3]),  mB1 = pk2(vB[10], vB[10]);
#pragma unroll
      for (int p = 0; p < 8; p++) { const u64 s = c_cf[136 + p]; aA[p] = s; aB[p] = s; }
#pragma unroll
      for (int p = 0; p < 8; p++) {
        const u64 w0 = c_cf[64 + 2 * p], w1 = c_cf[64 + 2 * p + 1];
        aA[p] = ffma2(mA0, w0, aA[p]);  aA[p] = ffma2(mA1, w1, aA[p]);
        aB[p] = ffma2(mB0, w0, aB[p]);  aB[p] = ffma2(mB1, w1, aB[p]);
      }
      float rAl, rAh, rBl, rBh;
      branch_reduce2(aA, aB, lane, rAl, rAh, rBl, rBh);
      if (sel == 1) { finAlo = rAl; finAhi = rAh; finBlo = rBl; finBhi = rBh; }
    }
    // ---- branch 2 ----
    {
      const u64 mA0 = pk2(vA[4], vA[4]),  mA1 = pk2(vA[11], vA[11]);
      const u64 mB0 = pk2(vB[4], vB[4]),  mB1 = pk2(vB[11], vB[11]);
#pragma unroll
      for (int p = 0; p < 8; p++) { const u64 s = c_cf[144 + p]; aA[p] = s; aB[p] = s; }
#pragma unroll
      for (int p = 0; p < 8; p++) {
        const u64 w0 = c_cf[80 + 2 * p], w1 = c_cf[80 + 2 * p + 1];
        aA[p] = ffma2(mA0, w0, aA[p]);  aA[p] = ffma2(mA1, w1, aA[p]);
        aB[p] = ffma2(mB0, w0, aB[p]);  aB[p] = ffma2(mB1, w1, aB[p]);
      }
      float rAl, rAh, rBl, rBh;
      branch_reduce2(aA, aB, lane, rAl, rAh, rBl, rBh);
      if (sel == 2) { finAlo = rAl; finAhi = rAh; finBlo = rBl; finBhi = rBh; }
    }
    // ---- branch 3 ----
    {
      const u64 mA0 = pk2(vA[0], vA[0]),   mA1 = pk2(vA[1], vA[1]);
      const u64 mA2 = pk2(vA[12], vA[12]), mA3 = pk2(vA[13], vA[13]);
      const u64 mB0 = pk2(vB[0], vB[0]),   mB1 = pk2(vB[1], vB[1]);
      const u64 mB2 = pk2(vB[12], vB[12]), mB3 = pk2(vB[13], vB[13]);
#pragma unroll
      for (int p = 0; p < 8; p++) { const u64 s = c_cf[152 + p]; aA[p] = s; aB[p] = s; }
#pragma unroll
      for (int p = 0; p < 8; p++) {
        const u64 w0 = c_cf[96 + 4 * p],     w1 = c_cf[96 + 4 * p + 1];
        const u64 w2 = c_cf[96 + 4 * p + 2], w3 = c_cf[96 + 4 * p + 3];
        aA[p] = ffma2(mA0, w0, aA[p]);  aA[p] = ffma2(mA1, w1, aA[p]);
        aA[p] = ffma2(mA2, w2, aA[p]);  aA[p] = ffma2(mA3, w3, aA[p]);
        aB[p] = ffma2(mB0, w0, aB[p]);  aB[p] = ffma2(mB1, w1, aB[p]);
        aB[p] = ffma2(mB2, w2, aB[p]);  aB[p] = ffma2(mB3, w3, aB[p]);
      }
      float rAl, rAh, rBl, rBh;
      branch_reduce2(aA, aB, lane, rAl, rAh, rBl, rBh);
      if (sel == 3) { finAlo = rAl; finAhi = rAh; finBlo = rBl; finBhi = rBh; }
    }

    // raw max out (no relu — applied in affine_kernel)
    __stcs(reinterpret_cast<float2*>(out + (size_t)n * 64) + lane,
           make_float2(finAlo, finAhi));
    if (bv) {
      __stcs(reinterpret_cast<float2*>(out + (size_t)nB * 64) + lane,
             make_float2(finBlo, finBhi));
    }
    __syncwarp();

    buf ^= 2;
  }

  // block-level deterministic moment reduction; transposed store
#pragma unroll
  for (int i = 0; i < NMOM; i++) {
#pragma unroll
    for (int o = 16; o; o >>= 1) mom[i] += shflf(mom[i], o);
  }
  if (lane == 0) {
#pragma unroll
    for (int i = 0; i < NMOM; i++) s_red[warp][i] = mom[i];
  }
  __syncthreads();
  for (int t = tid; t < NMOM; t += WARPS_C * 32) {
    float s = 0.f;
#pragma unroll
    for (int w = 0; w < WARPS_C; w++) s += s_red[w][t];
    g_partials[t * BLOCKS_C + blockIdx.x] = s;   // [mom][block]
  }
}

// ---------------------------------------------------------------------------
// Deterministic parallel reduction: one block per moment, coalesced reads.
__global__ __launch_bounds__(256)
void reduce_kernel() {
  __shared__ float sh[256];
  const int t = blockIdx.x;       // moment index
  const int x = threadIdx.x;
  float s = 0.f;
  for (int i = x; i < BLOCKS_C; i += 256)   // fixed order -> deterministic
    s += g_partials[t * BLOCKS_C + i];
  sh[x] = s;
  __syncthreads();
#pragma unroll
  for (int o = 128; o; o >>= 1) {
    if (x < o) sh[x] += sh[x + o];
    __syncthreads();
  }
  if (x == 0) g_mom_sum[t] = sh[0];
}

// ---------------------------------------------------------------------------
// Per-channel scale & shift from the reduced moments.
__global__ void finalize_kernel(const float* __restrict__ w1, const float* __restrict__ w2,
                                const float* __restrict__ w3, const float* __restrict__ w4,
                                const float* __restrict__ gm_, const float* __restrict__ bt_,
                                double tot) {
  __shared__ double mom[NMOM];
  const int t = threadIdx.x;
  if (t < NMOM) mom[t] = (double)g_mom_sum[t] / tot;
  __syncthreads();
  if (t >= 64) return;
  const int br = t >> 4, uu = t & 15;

  double mu = 0.0, E2 = 0.0;
  double wv[8];
  if (br == 0) {
    const int L[8] = {0, 1, 2, 5, 6, 7, 8, 9};
    for (int c = 0; c < 8; c++) wv[c] = (double)w1[uu * 8 + c];
    for (int c = 0; c < 8; c++) mu += wv[c] * mom[L[c]];
    for (int i = 0; i < 8; i++)
      for (int j = 0; j < 8; j++) {
        int a = i < j ? i : j, d = i < j ? j : i;
        E2 += wv[i] * wv[j] * mom[14 + a * 8 - a * (a - 1) / 2 + (d - a)];
      }
  } else if (br == 1) {
    wv[0] = (double)w2[uu * 2]; wv[1] = (double)w2[uu * 2 + 1];
    mu = wv[0] * mom[3] + wv[1] * mom[10];
    E2 = wv[0] * wv[0] * mom[50] + 2.0 * wv[0] * wv[1] * mom[51] + wv[1] * wv[1] * mom[52];
  } else if (br == 2) {
    wv[0] = (double)w3[uu * 2]; wv[1] = (double)w3[uu * 2 + 1];
    mu = wv[0] * mom[4] + wv[1] * mom[11];
    E2 = wv[0] * wv[0] * mom[53] + 2.0 * wv[0] * wv[1] * mom[54] + wv[1] * wv[1] * mom[55];
  } else {
    const int m1i[4] = {0, 1, 12, 13};
    const int S[4][4] = {{14, 15, 56, 57}, {15, 22, 58, 59}, {56, 58, 60, 61}, {57, 59, 61, 62}};
    for (int c = 0; c < 4; c++) wv[c] = (double)w4[uu * 4 + c];
    for (int c = 0; c < 4; c++) mu += wv[c] * mom[m1i[c]];
    for (int i = 0; i < 4; i++)
      for (int j = 0; j < 4; j++) E2 += wv[i] * wv[j] * mom[S[i][j]];
  }
  const double gmv = (double)gm_[br * 16 + uu];
  const double btv = (double)bt_[br * 16 + uu];
  const double var = E2 - mu * mu;
  const double invs = 1.0 / sqrt(var + (double)1e-3f);
  const double scale = gmv * invs;
  g_affine[t]      = (float)scale;
  g_affine[64 + t] = (float)(btv - mu * scale);
}

// ---------------------------------------------------------------------------
// In-place: out = relu(scale[ch]*out + shift[ch]). ch quad loop-invariant.
__global__ __launch_bounds__(256)
void affine_kernel(float* __restrict__ out, int total) {
  const int n4     = total >> 2;
  const int stride = gridDim.x * blockDim.x;   // *4 % 64 == 0
  const int idx    = blockIdx.x * blockDim.x + threadIdx.x;
  const int cb     = (idx << 2) & 63;
  const float s0 = g_affine[cb],     s1 = g_affine[cb + 1];
  const float s2 = g_affine[cb + 2], s3 = g_affine[cb + 3];
  const float h0 = g_affine[64 + cb],     h1 = g_affine[64 + cb + 1];
  const float h2 = g_affine[64 + cb + 2], h3 = g_affine[64 + cb + 3];
  float4* p = reinterpret_cast<float4*>(out);
  for (int i = idx; i < n4; i += stride) {
    float4 r = p[i];
    r.x = fmaxf(fmaf(r.x, s0, h0), 0.f);
    r.y = fmaxf(fmaf(r.y, s1, h1), 0.f);
    r.z = fmaxf(fmaf(r.z, s2, h2), 0.f);
    r.w = fmaxf(fmaf(r.w, s3, h3), 0.f);
    p[i] = r;
  }
}

// ---------------------------------------------------------------------------
extern "C" void kernel_launch(void* const* d_in, const int* in_sizes, int n_in,
                              void* d_out, int out_size) {
  const float* feats = (const float*)d_in[0];
  const float* w1    = (const float*)d_in[1];
  const float* w2    = (const float*)d_in[2];
  const float* w3    = (const float*)d_in[3];
  const float* w4    = (const float*)d_in[4];
  const float* gmm   = (const float*)d_in[5];
  const float* bta   = (const float*)d_in[6];
  const int*   nump  = (const int*)d_in[7];
  const int*   coors = (const int*)d_in[8];
  float*       out   = (float*)d_out;

  const int nP = in_sizes[7];
  const double tot = (double)nP * (double)MPTS;

  shift_kernel<<<1, 1>>>();   // ncu window shifters: land capture on fused
  shift_kernel<<<1, 1>>>();

  pack_kernel<<<1, 64>>>(w1, w2, w3, w4);
  void* gsrc = nullptr;
  cudaGetSymbolAddress(&gsrc, g_coeff);
  cudaMemcpyToSymbolAsync(c_cf, gsrc, 160 * sizeof(u64), 0,
                          cudaMemcpyDeviceToDevice, 0);

  fused_kernel<<<BLOCKS_C, WARPS_C * 32>>>(feats, nump, coors, out, nP);
  reduce_kernel<<<NMOM, 256>>>();
  finalize_kernel<<<1, 64>>>(w1, w2, w3, w4, gmm, bta, tot);
  affine_kernel<<<1480, 256>>>(out, out_size);
}

// round 16
// speedup vs baseline: 2.3199x; 2.3199x over previous
#include <cuda_runtime.h>
#include <math.h>

// ---------------------------------------------------------------------------
// RadarPillarFeatureNet on GB300 — single fused data pass (verified R12 fused):
//   pack_kernel:   raw weights -> packed pair layout -> __constant__ c_cf
//   fused_kernel:  TWO pillars/iter: RAW channel max (f32x2 GEMVs, dual u64
//                  butterfly) AND 63-moment accumulation; transposed partials.
//   finalize:      merged reduce(888 partials/moment) + layernorm fold.
//   affine:        out = relu(scale*rawmax + shift)  (scale>0 => commutes).
// ---------------------------------------------------------------------------

typedef unsigned long long u64;

namespace {
constexpr int   MPTS   = 32;
constexpr float VXc = 0.2f, VYc = 0.2f, XOFF = 0.1f, YOFF = -39.9f;
constexpr int   NMOM   = 63;
constexpr int   WARPS_C = 4;
constexpr int   BLOCKS_C = 888;
}

__device__ float g_partials[NMOM * BLOCKS_C];   // [mom][block] (transposed)
// Packed RAW weights (float2 "u" pairs), viewed as u64[160]:
//  [0..63] b0 p*8+c | [64..79] b1 | [80..95] b2 | [96..127] b3 | [128..159] zeros
__device__ __align__(16) float g_coeff[320];
__constant__ __align__(16) u64 c_cf[160];
__device__ float g_affine[128];   // [0..63] scale, [64..127] shift

__device__ __forceinline__ u64 pk2(float a, float b) {
  u64 r; asm("mov.b64 %0, {%1,%2};" : "=l"(r) : "f"(a), "f"(b)); return r;
}
__device__ __forceinline__ u64 ffma2(u64 a, u64 b, u64 c) {
  u64 d; asm("fma.rn.f32x2 %0, %1, %2, %3;" : "=l"(d) : "l"(a), "l"(b), "l"(c)); return d;
}
__device__ __forceinline__ u64 add2(u64 a, u64 b) {
  u64 d; asm("add.rn.f32x2 %0, %1, %2;" : "=l"(d) : "l"(a), "l"(b)); return d;
}
__device__ __forceinline__ u64 max2(u64 a, u64 b) {
  float al, ah, bl, bh;
  asm("mov.b64 {%0,%1}, %2;" : "=f"(al), "=f"(ah) : "l"(a));
  asm("mov.b64 {%0,%1}, %2;" : "=f"(bl), "=f"(bh) : "l"(b));
  return pk2(fmaxf(al, bl), fmaxf(ah, bh));
}
__device__ __forceinline__ u64 shfl64(u64 x, int o) {
  return __shfl_xor_sync(0xffffffffu, x, o);
}
__device__ __forceinline__ void cp16(unsigned s, const void* g) {
  asm volatile("cp.async.cg.shared.global [%0], [%1], 16;" :: "r"(s), "l"(g));
}

// f32x2-packed warp sums for the 5 feature columns.
__device__ __forceinline__ void make_feat(const float f[9], int np, float cx, float cy,
                                          int lane, float v[14]) {
  u64 s01 = pk2(f[0], f[1]);
  u64 s23 = pk2(f[2], f[3]);
  float s4 = f[4];
#pragma unroll
  for (int o = 16; o; o >>= 1) {
    s01 = add2(s01, shfl64(s01, o));
    s23 = add2(s23, shfl64(s23, o));
    s4 += __shfl_xor_sync(0xffffffffu, s4, o);
  }
  float sx, sy, sz, s3;
  asm("mov.b64 {%0,%1}, %2;" : "=f"(sx), "=f"(sy) : "l"(s01));
  asm("mov.b64 {%0,%1}, %2;" : "=f"(sz), "=f"(s3) : "l"(s23));
  float inv  = 1.0f / (float)np;
  float mask = (lane < np) ? 1.0f : 0.0f;
  v[0] = (f[0] - cx) * mask;
  v[1] = (f[1] - cy) * mask;
  v[2] = f[2] * mask;  v[3] = f[3] * mask;  v[4] = f[4] * mask;
  v[5] = f[5] * mask;  v[6] = f[6] * mask;  v[7] = f[7] * mask;  v[8] = f[8] * mask;
  v[9]  = (f[0] - sx * inv) * mask;
  v[10] = (f[1] - sy * inv) * mask;
  v[11] = (f[2] - sz * inv) * mask;
  v[12] = (f[3] - s3 * inv) * mask;
  v[13] = (f[4] - s4 * inv) * mask;
}

// Dual butterfly reduce (two pillars, shared predicates) — verified R12 form.
__device__ __forceinline__ void branch_reduce2(u64 aA[8], u64 aB[8], int lane,
                                               u64& rA, u64& rB) {
#pragma unroll
  for (int b = 2; b >= 0; b--) {
    const int  o    = 1 << b;
    const int  half = 1 << b;
    const bool bit  = (lane >> b) & 1;
#pragma unroll
    for (int i = 0; i < half; i++) {
      const u64 sA = bit ? aA[i] : aA[i + half];
      const u64 sB = bit ? aB[i] : aB[i + half];
      const u64 gA = __shfl_xor_sync(0xffffffffu, sA, o);
      const u64 gB = __shfl_xor_sync(0xffffffffu, sB, o);
      aA[i] = max2(bit ? aA[i + half] : aA[i], gA);
      aB[i] = max2(bit ? aB[i + half] : aB[i], gB);
    }
  }
  u64 a = aA[0], b2_ = aB[0];
  a   = max2(a,   shfl64(a, 8));    b2_ = max2(b2_, shfl64(b2_, 8));
  a   = max2(a,   shfl64(a, 16));   b2_ = max2(b2_, shfl64(b2_, 16));
  rA = a; rB = b2_;
}

// Scalar moment accumulation for one pillar's feature vector v.
__device__ __forceinline__ void accum_moments(float acc[NMOM], const float v[14]) {
#pragma unroll
  for (int i = 0; i < 14; i++) acc[i] += v[i];
  const int L1[8] = {0, 1, 2, 5, 6, 7, 8, 9};
  int k = 14;
#pragma unroll
  for (int i = 0; i < 8; i++)
#pragma unroll
    for (int j = i; j < 8; j++) acc[k++] += v[L1[i]] * v[L1[j]];
  acc[50] += v[3] * v[3];   acc[51] += v[3] * v[10];  acc[52] += v[10] * v[10];
  acc[53] += v[4] * v[4];   acc[54] += v[4] * v[11];  acc[55] += v[11] * v[11];
  acc[56] += v[0] * v[12];  acc[57] += v[0] * v[13];
  acc[58] += v[1] * v[12];  acc[59] += v[1] * v[13];
  acc[60] += v[12] * v[12]; acc[61] += v[12] * v[13]; acc[62] += v[13] * v[13];
}

// ---------------------------------------------------------------------------
__global__ void shift_kernel() {}   // ncu capture-window shifter (no-op)

// Pack RAW weights into the pair layout (shifts = 0).
__global__ void pack_kernel(const float* __restrict__ w1, const float* __restrict__ w2,
                            const float* __restrict__ w3, const float* __restrict__ w4) {
  const int t = threadIdx.x;
  if (t >= 64) return;
  const int br = t >> 4, uu = t & 15, half = uu & 1, p = uu >> 1;
  g_coeff[256 + t] = 0.f;
  if (br == 0) {
    for (int c = 0; c < 8; c++) g_coeff[(p * 8 + c) * 2 + half] = w1[uu * 8 + c];
  } else if (br == 1) {
    for (int c = 0; c < 2; c++) g_coeff[(64 + p * 2 + c) * 2 + half] = w2[uu * 2 + c];
  } else if (br == 2) {
    for (int c = 0; c < 2; c++) g_coeff[(80 + p * 2 + c) * 2 + half] = w3[uu * 2 + c];
  } else {
    for (int c = 0; c < 4; c++) g_coeff[(96 + p * 4 + c) * 2 + half] = w4[uu * 4 + c];
  }
}

// ---------------------------------------------------------------------------
__device__ __forceinline__ void stage_pillar(const float* feats, int n,
                                             float* dst, int lane) {
  const float4* src = reinterpret_cast<const float4*>(feats + (size_t)n * 288);
  unsigned base = (unsigned)__cvta_generic_to_shared(dst);
  cp16(base + lane * 16, src + lane);
  cp16(base + (lane + 32) * 16, src + lane + 32);
  if (lane < 8) cp16(base + (lane + 64) * 16, src + lane + 64);
}

// Fused: raw per-channel max into out, AND moment partials into g_partials.
__global__ __launch_bounds__(WARPS_C * 32, 3)
void fused_kernel(const float* __restrict__ feats, const int* __restrict__ nump,
                  const int* __restrict__ coors, float* __restrict__ out, int nP) {
  __shared__ __align__(16) float s_stage[WARPS_C][4][288];
  __shared__ float s_red[WARPS_C][NMOM];
  const int tid  = threadIdx.x;
  const int warp = tid >> 5;
  const int lane = tid & 31;

  const int gw = blockIdx.x * WARPS_C + warp;
  const int W  = BLOCKS_C * WARPS_C;
  const int sel = lane >> 3;

  float mom[NMOM];
#pragma unroll
  for (int i = 0; i < NMOM; i++) mom[i] = 0.f;

  if (gw < nP)     stage_pillar(feats, gw,     &s_stage[warp][0][0], lane);
  if (gw + W < nP) stage_pillar(feats, gw + W, &s_stage[warp][1][0], lane);
  asm volatile("cp.async.commit_group;");

  int buf = 0;
  for (int n = gw; n < nP; n += 2 * W) {
    const int nB = n + W;
    const bool bv = nB < nP;

    const int   npA = nump[n];
    const float cxA = (float)coors[n * 4 + 3] * VXc + XOFF;
    const float cyA = (float)coors[n * 4 + 2] * VYc + YOFF;
    int npB = 1; float cxB = 0.f, cyB = 0.f;
    if (bv) {
      npB = nump[nB];
      cxB = (float)coors[nB * 4 + 3] * VXc + XOFF;
      cyB = (float)coors[nB * 4 + 2] * VYc + YOFF;
    }

    const int nnA = n + 2 * W, nnB = n + 3 * W;
    if (nnA < nP) stage_pillar(feats, nnA, &s_stage[warp][buf ^ 2][0], lane);
    if (nnB < nP) stage_pillar(feats, nnB, &s_stage[warp][(buf ^ 2) + 1][0], lane);
    asm volatile("cp.async.commit_group;");
    asm volatile("cp.async.wait_group 1;");
    __syncwarp();

    float vA[14], vB[14];
    {
      const float* sA = s_stage[warp][buf];
      float fA[9];
#pragma unroll
      for (int c = 0; c < 9; c++) fA[c] = sA[lane * 9 + c];
      make_feat(fA, npA, cxA, cyA, lane, vA);
    }
    if (bv) {
      const float* sB = s_stage[warp][buf + 1];
      float fB[9];
#pragma unroll
      for (int c = 0; c < 9; c++) fB[c] = sB[lane * 9 + c];
      make_feat(fB, npB, cxB, cyB, lane, vB);
    } else {
#pragma unroll
      for (int c = 0; c < 14; c++) vB[c] = 0.f;
    }

    // moments (both pillars; vB==0 when invalid)
    accum_moments(mom, vA);
    accum_moments(mom, vB);

    u64 finA = 0, finB = 0;
    u64 aA[8], aB[8];
    // ---- branch 0 ----
    {
      const int M[8] = {0, 1, 2, 5, 6, 7, 8, 9};
#pragma unroll
      for (int p = 0; p < 8; p++) { const u64 s = c_cf[128 + p]; aA[p] = s; aB[p] = s; }
#pragma unroll
      for (int c = 0; c < 8; c++) {
        const u64 mA = pk2(vA[M[c]], vA[M[c]]);
        const u64 mB = pk2(vB[M[c]], vB[M[c]]);
#pragma unroll
        for (int p = 0; p < 8; p++) {
          const u64 w = c_cf[p * 8 + c];
          aA[p] = ffma2(mA, w, aA[p]);
          aB[p] = ffma2(mB, w, aB[p]);
        }
      }
      u64 rA, rB;
      branch_reduce2(aA, aB, lane, rA, rB);
      if (sel == 0) { finA = rA; finB = rB; }
    }
    // ---- branch 1 ----
    {
      const u64 mA0 = pk2(vA[3], vA[3]),  mA1 = pk2(vA[10], vA[10]);
      const u64 mB0 = pk2(vB[3], vB[3]),  mB1 = pk2(vB[10], vB[10]);
#pragma unroll
      for (int p = 0; p < 8; p++) { const u64 s = c_cf[136 + p]; aA[p] = s; aB[p] = s; }
#pragma unroll
      for (int p = 0; p < 8; p++) {
        const u64 w0 = c_cf[64 + 2 * p], w1 = c_cf[64 + 2 * p + 1];
        aA[p] = ffma2(mA0, w0, aA[p]);  aA[p] = ffma2(mA1, w1, aA[p]);
        aB[p] = ffma2(mB0, w0, aB[p]);  aB[p] = ffma2(mB1, w1, aB[p]);
      }
      u64 rA, rB;
      branch_reduce2(aA, aB, lane, rA, rB);
      if (sel == 1) { finA = rA; finB = rB; }
    }
    // ---- branch 2 ----
    {
      const u64 mA0 = pk2(vA[4], vA[4]),  mA1 = pk2(vA[11], vA[11]);
      const u64 mB0 = pk2(vB[4], vB[4]),  mB1 = pk2(vB[11], vB[11]);
#pragma unroll
      for (int p = 0; p < 8; p++) { const u64 s = c_cf[144 + p]; aA[p] = s; aB[p] = s; }
#pragma unroll
      for (int p = 0; p < 8; p++) {
        const u64 w0 = c_cf[80 + 2 * p], w1 = c_cf[80 + 2 * p + 1];
        aA[p] = ffma2(mA0, w0, aA[p]);  aA[p] = ffma2(mA1, w1, aA[p]);
        aB[p] = ffma2(mB0, w0, aB[p]);  aB[p] = ffma2(mB1, w1, aB[p]);
      }
      u64 rA, rB;
      branch_reduce2(aA, aB, lane, rA, rB);
      if (sel == 2) { finA = rA; finB = rB; }
    }
    // ---- branch 3 ----
    {
      const u64 mA0 = pk2(vA[0], vA[0]),   mA1 = pk2(vA[1], vA[1]);
      const u64 mA2 = pk2(vA[12], vA[12]), mA3 = pk2(vA[13], vA[13]);
      const u64 mB0 = pk2(vB[0], vB[0]),   mB1 = pk2(vB[1], vB[1]);
      const u64 mB2 = pk2(vB[12], vB[12]), mB3 = pk2(vB[13], vB[13]);
#pragma unroll
      for (int p = 0; p < 8; p++) { const u64 s = c_cf[152 + p]; aA[p] = s; aB[p] = s; }
#pragma unroll
      for (int p = 0; p < 8; p++) {
        const u64 w0 = c_cf[96 + 4 * p],     w1 = c_cf[96 + 4 * p + 1];
        const u64 w2 = c_cf[96 + 4 * p + 2], w3 = c_cf[96 + 4 * p + 3];
        aA[p] = ffma2(mA0, w0, aA[p]);  aA[p] = ffma2(mA1, w1, aA[p]);
        aA[p] = ffma2(mA2, w2, aA[p]);  aA[p] = ffma2(mA3, w3, aA[p]);
        aB[p] = ffma2(mB0, w0, aB[p]);  aB[p] = ffma2(mB1, w1, aB[p]);
        aB[p] = ffma2(mB2, w2, aB[p]);  aB[p] = ffma2(mB3, w3, aB[p]);
      }
      u64 rA, rB;
      branch_reduce2(aA, aB, lane, rA, rB);
      if (sel == 3) { finA = rA; finB = rB; }
    }

    // raw max out (no relu — applied in affine). Plain store: keep `out`
    // L2-resident so the affine pass mostly hits L2.
    {
      float lo, hi;
      asm("mov.b64 {%0,%1}, %2;" : "=f"(lo), "=f"(hi) : "l"(finA));
      reinterpret_cast<float2*>(out + (size_t)n * 64)[lane] = make_float2(lo, hi);
    }
    if (bv) {
      float lo, hi;
      asm("mov.b64 {%0,%1}, %2;" : "=f"(lo), "=f"(hi) : "l"(finB));
      reinterpret_cast<float2*>(out + (size_t)nB * 64)[lane] = make_float2(lo, hi);
    }
    __syncwarp();

    buf ^= 2;
  }

  // block-level deterministic moment reduction; transposed store
#pragma unroll
  for (int i = 0; i < NMOM; i++) {
#pragma unroll
    for (int o = 16; o; o >>= 1) mom[i] += __shfl_xor_sync(0xffffffffu, mom[i], o);
  }
  if (lane == 0) {
#pragma unroll
    for (int i = 0; i < NMOM; i++) s_red[warp][i] = mom[i];
  }
  __syncthreads();
  for (int t = tid; t < NMOM; t += WARPS_C * 32) {
    float s = 0.f;
#pragma unroll
    for (int w = 0; w < WARPS_C; w++) s += s_red[w][t];
    g_partials[t * BLOCKS_C + blockIdx.x] = s;   // [mom][block]
  }
}

// ---------------------------------------------------------------------------
// Merged reduce + finalize: one 256-thread block.
// Phase 1: 4 threads per moment sum 888 partials (fixed order, deterministic).
// Phase 2: 63 threads combine; 64 threads do the layernorm fold math.
__global__ __launch_bounds__(256)
void finalize_kernel(const float* __restrict__ w1, const float* __restrict__ w2,
                     const float* __restrict__ w3, const float* __restrict__ w4,
                     const float* __restrict__ gm_, const float* __restrict__ bt_,
                     double tot) {
  __shared__ float sh[256];
  __shared__ double mom[NMOM];
  const int x = threadIdx.x;
  const int t = x >> 2, s = x & 3;
  float acc = 0.f;
  if (t < NMOM) {
    for (int i = s; i < BLOCKS_C; i += 4)   // fixed order -> deterministic
      acc += g_partials[t * BLOCKS_C + i];
  }
  sh[x] = acc;
  __syncthreads();
  if (x < NMOM) {
    double d = ((double)sh[4 * x] + (double)sh[4 * x + 1]) +
               ((double)sh[4 * x + 2] + (double)sh[4 * x + 3]);
    mom[x] = d / tot;
  }
  __syncthreads();
  if (x >= 64) return;
  const int br = x >> 4, uu = x & 15;

  double mu = 0.0, E2 = 0.0;
  double wv[8];
  if (br == 0) {
    const int L[8] = {0, 1, 2, 5, 6, 7, 8, 9};
    for (int c = 0; c < 8; c++) wv[c] = (double)w1[uu * 8 + c];
    for (int c = 0; c < 8; c++) mu += wv[c] * mom[L[c]];
    for (int i = 0; i < 8; i++)
      for (int j = 0; j < 8; j++) {
        int a = i < j ? i : j, d = i < j ? j : i;
        E2 += wv[i] * wv[j] * mom[14 + a * 8 - a * (a - 1) / 2 + (d - a)];
      }
  } else if (br == 1) {
    wv[0] = (double)w2[uu * 2]; wv[1] = (double)w2[uu * 2 + 1];
    mu = wv[0] * mom[3] + wv[1] * mom[10];
    E2 = wv[0] * wv[0] * mom[50] + 2.0 * wv[0] * wv[1] * mom[51] + wv[1] * wv[1] * mom[52];
  } else if (br == 2) {
    wv[0] = (double)w3[uu * 2]; wv[1] = (double)w3[uu * 2 + 1];
    mu = wv[0] * mom[4] + wv[1] * mom[11];
    E2 = wv[0] * wv[0] * mom[53] + 2.0 * wv[0] * wv[1] * mom[54] + wv[1] * wv[1] * mom[55];
  } else {
    const int m1i[4] = {0, 1, 12, 13};
    const int S[4][4] = {{14, 15, 56, 57}, {15, 22, 58, 59}, {56, 58, 60, 61}, {57, 59, 61, 62}};
    for (int c = 0; c < 4; c++) wv[c] = (double)w4[uu * 4 + c];
    for (int c = 0; c < 4; c++) mu += wv[c] * mom[m1i[c]];
    for (int i = 0; i < 4; i++)
      for (int j = 0; j < 4; j++) E2 += wv[i] * wv[j] * mom[S[i][j]];
  }
  const double gmv = (double)gm_[br * 16 + uu];
  const double btv = (double)bt_[br * 16 + uu];
  const double var = E2 - mu * mu;
  const double invs = 1.0 / sqrt(var + (double)1e-3f);
  const double scale = gmv * invs;
  g_affine[x]      = (float)scale;
  g_affine[64 + x] = (float)(btv - mu * scale);
}

// ---------------------------------------------------------------------------
// In-place: out = relu(scale[ch]*out + shift[ch]). ch quad loop-invariant.
__global__ __launch_bounds__(256)
void affine_kernel(float* __restrict__ out, int total) {
  const int n4     = total >> 2;
  const int stride = gridDim.x * blockDim.x;   // *4 % 64 == 0
  const int idx    = blockIdx.x * blockDim.x + threadIdx.x;
  const int cb     = (idx << 2) & 63;
  const float s0 = g_affine[cb],     s1 = g_affine[cb + 1];
  const float s2 = g_affine[cb + 2], s3 = g_affine[cb + 3];
  const float h0 = g_affine[64 + cb],     h1 = g_affine[64 + cb + 1];
  const float h2 = g_affine[64 + cb + 2], h3 = g_affine[64 + cb + 3];
  float4* p = reinterpret_cast<float4*>(out);
  for (int i = idx; i < n4; i += stride) {
    float4 r = p[i];
    r.x = fmaxf(fmaf(r.x, s0, h0), 0.f);
    r.y = fmaxf(fmaf(r.y, s1, h1), 0.f);
    r.z = fmaxf(fmaf(r.z, s2, h2), 0.f);
    r.w = fmaxf(fmaf(r.w, s3, h3), 0.f);
    p[i] = r;
  }
}

// ---------------------------------------------------------------------------
extern "C" void kernel_launch(void* const* d_in, const int* in_sizes, int n_in,
                              void* d_out, int out_size) {
  const float* feats = (const float*)d_in[0];
  const float* w1    = (const float*)d_in[1];
  const float* w2    = (const float*)d_in[2];
  const float* w3    = (const float*)d_in[3];
  const float* w4    = (const float*)d_in[4];
  const float* gmm   = (const float*)d_in[5];
  const float* bta   = (const float*)d_in[6];
  const int*   nump  = (const int*)d_in[7];
  const int*   coors = (const int*)d_in[8];
  float*       out   = (float*)d_out;

  const int nP = in_sizes[7];
  const double tot = (double)nP * (double)MPTS;

  shift_kernel<<<1, 1>>>();   // keep fused as the 4th launch for ncu capture
  shift_kernel<<<1, 1>>>();

  pack_kernel<<<1, 64>>>(w1, w2, w3, w4);
  void* gsrc = nullptr;
  cudaGetSymbolAddress(&gsrc, g_coeff);
  cudaMemcpyToSymbolAsync(c_cf, gsrc, 160 * sizeof(u64), 0,
                          cudaMemcpyDeviceToDevice, 0);

  fused_kernel<<<BLOCKS_C, WARPS_C * 32>>>(feats, nump, coors, out, nP);
  finalize_kernel<<<1, 256>>>(w1, w2, w3, w4, gmm, bta, tot);
  affine_kernel<<<1480, 256>>>(out, out_size);
}